// round 6
// baseline (speedup 1.0000x reference)
#include <cuda_runtime.h>
#include <cstdint>
#include <math.h>

#define K1T 1152
#define K2T 2432
#define NCH1 36
#define NCH2 76

__device__ float g_y[(size_t)131072 * 256];
__device__ float g_xr[(size_t)131072 * 128];
__device__ float g_sq[131072];
__device__ float g_asum[131072];
__device__ float g_wyT[256 * K1T];
__device__ float g_wlT[256 * K2T];
__device__ float g_bsum[256];

__device__ __forceinline__ uint32_t smem_u32(const void* p) {
    uint32_t a;
    asm("{ .reg .u64 t; cvta.to.shared.u64 t, %1; cvt.u32.u64 %0, t; }" : "=r"(a) : "l"(p));
    return a;
}
__device__ __forceinline__ float tf32r(float f) {
    uint32_t u; asm("cvt.rna.tf32.f32 %0, %1;" : "=r"(u) : "f"(f));
    return __uint_as_float(u);
}
// c-major chunk permutation: k(in 32) = ks*8 + c + 4*hi  ->  slot = c*8 + ks*2 + hi
__device__ __forceinline__ int kperm(int k) {
    const int ks = (k >> 3) & 3, c = k & 3, hi = (k >> 2) & 1;
    return (k & ~31) | (c * 8 + ks * 2 + hi);
}
__device__ __forceinline__ void cpa16(uint32_t dst, const float* src, uint32_t sz) {
    asm volatile("cp.async.cg.shared.global [%0], [%1], 16, %2;" :: "r"(dst), "l"(src), "r"(sz));
}
#define CPA_COMMIT()  asm volatile("cp.async.commit_group;" ::: "memory")
#define CPA_WAIT1()   asm volatile("cp.async.wait_group 1;" ::: "memory")
#define CPA_WAIT0()   asm volatile("cp.async.wait_group 0;" ::: "memory")

__device__ __forceinline__ void mma8(float* d, uint32_t a0, uint32_t a1, uint32_t a2, uint32_t a3,
                                     uint32_t b0, uint32_t b1) {
    asm volatile("mma.sync.aligned.m16n8k8.row.col.f32.tf32.tf32.f32 "
                 "{%0,%1,%2,%3}, {%4,%5,%6,%7}, {%8,%9}, {%0,%1,%2,%3};"
                 : "+f"(d[0]), "+f"(d[1]), "+f"(d[2]), "+f"(d[3])
                 : "r"(a0), "r"(a1), "r"(a2), "r"(a3), "r"(b0), "r"(b1));
}

// As/Bs: 128 rows x 128B. 16B unit t at row r stored at t^(r&7).
// Unit t = 2*c + ks2 holds float4 = (k=8*2ks2+c, +c+4, k=8*(2ks2+1)+c, +c+4).
__device__ __forceinline__ void compute_chunk(const char* As, const char* Bs,
                                              float acc[2][8][4], int lane, int wm, int wn)
{
    const int r = lane >> 2, c = lane & 3;
    #pragma unroll
    for (int ks2 = 0; ks2 < 2; ks2++) {
        const int off = ((2 * c + ks2) ^ r) * 16;
        float4 aL[2], aH[2];
        #pragma unroll
        for (int mi = 0; mi < 2; mi++) {
            const int row0 = wm * 32 + mi * 16 + r;
            aL[mi] = *(const float4*)(As + row0 * 128 + off);
            aH[mi] = *(const float4*)(As + (row0 + 8) * 128 + off);
        }
        #pragma unroll
        for (int ni = 0; ni < 8; ni++) {
            const float4 bv = *(const float4*)(Bs + (wn * 64 + ni * 8 + r) * 128 + off);
            #pragma unroll
            for (int mi = 0; mi < 2; mi++) {
                mma8(acc[mi][ni], __float_as_uint(aL[mi].x), __float_as_uint(aH[mi].x),
                     __float_as_uint(aL[mi].y), __float_as_uint(aH[mi].y),
                     __float_as_uint(bv.x), __float_as_uint(bv.y));
                mma8(acc[mi][ni], __float_as_uint(aL[mi].z), __float_as_uint(aH[mi].z),
                     __float_as_uint(aL[mi].w), __float_as_uint(aH[mi].w),
                     __float_as_uint(bv.z), __float_as_uint(bv.w));
            }
        }
    }
}

// ---- prep ----
__global__ __launch_bounds__(256)
void k0a_w(const float* __restrict__ wy, const float* __restrict__ wl, const float* __restrict__ wp)
{
    const int co = blockIdx.x, t = threadIdx.x;
    __shared__ float red[256];
    float s = 0.f;
    for (int k = t; k < K1T; k += 256) {
        float v = wy[(size_t)k * 256 + co];
        s += v * v;
        g_wyT[(size_t)co * K1T + kperm(k)] = tf32r(v);
    }
    red[t] = s; __syncthreads();
    for (int o = 128; o > 0; o >>= 1) { if (t < o) red[t] += red[t + o]; __syncthreads(); }
    if (t == 0) g_bsum[co] = red[0];
    for (int k = t; k < K2T; k += 256) {
        float v = (k < 2304) ? wl[(size_t)k * 256 + co] : wp[(size_t)(k - 2304) * 256 + co];
        g_wlT[(size_t)co * K2T + kperm(k)] = tf32r(v);
    }
}
__global__ __launch_bounds__(256)
void k0b_x(const float* __restrict__ x)
{
    const int p = blockIdx.x * 8 + (threadIdx.x >> 5), lane = threadIdx.x & 31;
    float4 v = *(const float4*)(x + (size_t)p * 128 + lane * 4);
    float s = v.x * v.x + v.y * v.y + v.z * v.z + v.w * v.w;
    #pragma unroll
    for (int o = 16; o > 0; o >>= 1) s += __shfl_xor_sync(0xffffffff, s, o);
    if (lane == 0) g_sq[p] = s;
    float* dst = g_xr + (size_t)p * 128;
    const int ch = lane * 4;
    dst[kperm(ch)]     = tf32r(v.x);
    dst[kperm(ch + 1)] = tf32r(v.y);
    dst[kperm(ch + 2)] = tf32r(v.z);
    dst[kperm(ch + 3)] = tf32r(v.w);
}
__global__ __launch_bounds__(256)
void k0c_asum()
{
    const int p = blockIdx.x * 256 + threadIdx.x;
    const int h = (p >> 6) & 63, w = p & 63;
    float s = 0.f;
    #pragma unroll
    for (int dh = -1; dh <= 1; dh++)
        #pragma unroll
        for (int dw = -1; dw <= 1; dw++) {
            int hh = h + dh, ww = w + dw;
            if ((unsigned)hh < 64u && (unsigned)ww < 64u) s += g_sq[p + dh * 64 + dw];
        }
    g_asum[p] = s;
}

// ---- k1: yat conv ----
__global__ __launch_bounds__(256, 2)
void k1_yat(const float* __restrict__ alphap)
{
    extern __shared__ float smf[];
    const uint32_t sb = smem_u32(smf);
    const int tid = threadIdx.x, lane = tid & 31, wid = tid >> 5;
    const int wm = wid >> 1, wn = wid & 1;
    const int m_base = blockIdx.y * 128, c_base = blockIdx.x * 128;
    float* sbsum = smf + 24576;
    if (tid < 128) sbsum[tid] = g_bsum[c_base + tid];

    float acc[2][8][4];
    #pragma unroll
    for (int mi = 0; mi < 2; mi++)
        #pragma unroll
        for (int ni = 0; ni < 8; ni++)
            #pragma unroll
            for (int e = 0; e < 4; e++) acc[mi][ni][e] = 0.f;

    // hoisted staging state
    const int t8 = tid & 7, row0 = tid >> 3;
    int h0[4], w0[4];
    const float *xc[4], *wb[4];
    uint32_t sdst[4];
    #pragma unroll
    for (int p = 0; p < 4; p++) {
        const int r = row0 + 32 * p, m = m_base + r;
        h0[p] = (m >> 6) & 63; w0[p] = m & 63;
        xc[p] = g_xr + (size_t)m * 128 + t8 * 4;
        wb[p] = g_wyT + (size_t)(c_base + r) * K1T + t8 * 4;
        sdst[p] = (uint32_t)(r * 128 + ((t8 ^ (r & 7)) * 16));
    }

    auto stage = [&](int c, int b) {
        const int khw = c >> 2, c0 = (c & 3) * 32;
        const int dh = khw / 3 - 1, dw = khw % 3 - 1;
        const uint32_t base = sb + (uint32_t)b * 32768u;
        const int xoff = (dh * 64 + dw) * 128 + c0;
        #pragma unroll
        for (int p = 0; p < 4; p++) {
            const int hh = h0[p] + dh, ww = w0[p] + dw;
            const bool ok = (unsigned)hh < 64u && (unsigned)ww < 64u;
            cpa16(base + sdst[p], ok ? xc[p] + xoff : g_xr, ok ? 16u : 0u);
            cpa16(base + 16384u + sdst[p], wb[p] + c * 32, 16u);
        }
        CPA_COMMIT();
    };

    stage(0, 0); stage(1, 1);
    int b = 0;
    for (int c = 0; c < NCH1; c++) {
        if (c + 1 < NCH1) CPA_WAIT1(); else CPA_WAIT0();
        __syncthreads();
        if (c + 2 < NCH1) { int b2 = b + 2; if (b2 >= 3) b2 -= 3; stage(c + 2, b2); }
        compute_chunk((const char*)smf + b * 32768, (const char*)smf + b * 32768 + 16384,
                      acc, lane, wm, wn);
        if (++b == 3) b = 0;
    }

    const float scale = powf(16.f / log1pf(256.f), alphap[0]);
    #pragma unroll
    for (int mi = 0; mi < 2; mi++) {
        const int r0 = wm * 32 + mi * 16 + (lane >> 2);
        const int m0 = m_base + r0, m1 = m0 + 8;
        const float as0 = g_asum[m0], as1 = g_asum[m1];
        #pragma unroll
        for (int ni = 0; ni < 8; ni++) {
            const int cl = wn * 64 + ni * 8 + (lane & 3) * 2;
            const float bs0 = sbsum[cl], bs1 = sbsum[cl + 1];
            const float* d = acc[mi][ni];
            const float y00 = tf32r(d[0] * d[0] / (as0 + bs0 - 2.f * d[0] + 1e-5f) * scale);
            const float y01 = tf32r(d[1] * d[1] / (as0 + bs1 - 2.f * d[1] + 1e-5f) * scale);
            const float y10 = tf32r(d[2] * d[2] / (as1 + bs0 - 2.f * d[2] + 1e-5f) * scale);
            const float y11 = tf32r(d[3] * d[3] / (as1 + bs1 - 2.f * d[3] + 1e-5f) * scale);
            const int p0 = c_base + kperm(cl), p1 = c_base + kperm(cl + 1);
            g_y[(size_t)m0 * 256 + p0] = y00;
            g_y[(size_t)m0 * 256 + p1] = y01;
            g_y[(size_t)m1 * 256 + p0] = y10;
            g_y[(size_t)m1 * 256 + p1] = y11;
        }
    }
}

// ---- k2: lin conv + residual + 2x2 avg pool ----
__global__ __launch_bounds__(256, 2)
void k2_lin(float* __restrict__ out)
{
    extern __shared__ float smf[];
    const uint32_t sb = smem_u32(smf);
    const int tid = threadIdx.x, lane = tid & 31, wid = tid >> 5;
    const int wm = wid >> 1, wn = wid & 1;
    const int m_base = blockIdx.y * 128, c_base = blockIdx.x * 128;

    float acc[2][8][4];
    #pragma unroll
    for (int mi = 0; mi < 2; mi++)
        #pragma unroll
        for (int ni = 0; ni < 8; ni++)
            #pragma unroll
            for (int e = 0; e < 4; e++) acc[mi][ni][e] = 0.f;

    const int t8 = tid & 7, row0 = tid >> 3;
    int h0[4], w0[4];
    const float *yc[4], *wb[4];
    uint32_t sdst[4];
    #pragma unroll
    for (int p = 0; p < 4; p++) {
        const int r = row0 + 32 * p, m = m_base + r;
        h0[p] = (m >> 6) & 63; w0[p] = m & 63;
        yc[p] = g_y + (size_t)m * 256 + t8 * 4;
        wb[p] = g_wlT + (size_t)(c_base + r) * K2T + t8 * 4;
        sdst[p] = (uint32_t)(r * 128 + ((t8 ^ (r & 7)) * 16));
    }

    auto stage = [&](int c, int b) {
        const uint32_t base = sb + (uint32_t)b * 32768u;
        if (c < 72) {
            const int khw = c >> 3, c0 = (c & 7) * 32;
            const int dh = khw / 3 - 1, dw = khw % 3 - 1;
            const int yoff = (dh * 64 + dw) * 256 + c0;
            #pragma unroll
            for (int p = 0; p < 4; p++) {
                const int hh = h0[p] + dh, ww = w0[p] + dw;
                const bool ok = (unsigned)hh < 64u && (unsigned)ww < 64u;
                cpa16(base + sdst[p], ok ? yc[p] + yoff : g_y, ok ? 16u : 0u);
                cpa16(base + 16384u + sdst[p], wb[p] + c * 32, 16u);
            }
        } else {
            const int c0 = (c - 72) * 32;
            #pragma unroll
            for (int p = 0; p < 4; p++) {
                const int r = row0 + 32 * p;
                cpa16(base + sdst[p], g_xr + (size_t)(m_base + r) * 128 + c0 + t8 * 4, 16u);
                cpa16(base + 16384u + sdst[p], wb[p] + c * 32, 16u);
            }
        }
        CPA_COMMIT();
    };

    stage(0, 0); stage(1, 1);
    int b = 0;
    for (int c = 0; c < NCH2; c++) {
        if (c + 1 < NCH2) CPA_WAIT1(); else CPA_WAIT0();
        __syncthreads();
        if (c + 2 < NCH2) { int b2 = b + 2; if (b2 >= 3) b2 -= 3; stage(c + 2, b2); }
        compute_chunk((const char*)smf + b * 32768, (const char*)smf + b * 32768 + 16384,
                      acc, lane, wm, wn);
        if (++b == 3) b = 0;
    }

    __syncthreads();
    #pragma unroll
    for (int mi = 0; mi < 2; mi++) {
        const int r0 = wm * 32 + mi * 16 + (lane >> 2);
        #pragma unroll
        for (int ni = 0; ni < 8; ni++) {
            const int cl = wn * 64 + ni * 8 + (lane & 3) * 2;
            const float* d = acc[mi][ni];
            *(float2*)(smf + r0 * 132 + cl) = make_float2(d[0], d[1]);
            *(float2*)(smf + (r0 + 8) * 132 + cl) = make_float2(d[2], d[3]);
        }
    }
    __syncthreads();
    const int n = m_base >> 12, hp = ((m_base >> 6) & 63) >> 1;
    #pragma unroll
    for (int it = 0; it < 4; it++) {
        const int idx = tid + it * 256, pw = idx >> 5, ch = (idx & 31) * 4;
        float4 a0 = *(const float4*)(smf + (2 * pw) * 132 + ch);
        float4 a1 = *(const float4*)(smf + (2 * pw + 1) * 132 + ch);
        float4 a2 = *(const float4*)(smf + (64 + 2 * pw) * 132 + ch);
        float4 a3 = *(const float4*)(smf + (64 + 2 * pw + 1) * 132 + ch);
        *(float4*)(out + ((size_t)((n * 32 + hp) * 32 + pw)) * 256 + c_base + ch) =
            make_float4(0.25f * (a0.x + a1.x + a2.x + a3.x), 0.25f * (a0.y + a1.y + a2.y + a3.y),
                        0.25f * (a0.z + a1.z + a2.z + a3.z), 0.25f * (a0.w + a1.w + a2.w + a3.w));
    }
}

extern "C" void kernel_launch(void* const* d_in, const int* in_sizes, int n_in,
                              void* d_out, int out_size)
{
    const float* x  = (const float*)d_in[0];
    const float* wy = (const float*)d_in[1];
    const float* al = (const float*)d_in[2];
    const float* wl = (const float*)d_in[3];
    const float* wp = (const float*)d_in[4];
    float* out = (float*)d_out;

    cudaFuncSetAttribute(k1_yat, cudaFuncAttributeMaxDynamicSharedMemorySize, 98816);
    cudaFuncSetAttribute(k2_lin, cudaFuncAttributeMaxDynamicSharedMemorySize, 98304);

    k0a_w<<<256, 256>>>(wy, wl, wp);
    k0b_x<<<16384, 256>>>(x);
    k0c_asum<<<512, 256>>>();
    k1_yat<<<dim3(2, 1024), 256, 98816>>>(al);
    k2_lin<<<dim3(2, 1024), 256, 98304>>>(out);
}

// round 7
// speedup vs baseline: 1.0973x; 1.0973x over previous
#include <cuda_runtime.h>
#include <cstdint>
#include <math.h>

#define K1T 1152
#define K2T 2432
#define NCH1 36
#define NCH2 76

__device__ float g_y[(size_t)131072 * 256];
__device__ float g_xr[(size_t)131072 * 128];
__device__ float g_sq[131072];
__device__ float g_asum[131072];
__device__ float g_wyT[256 * K1T];
__device__ float g_wlT[256 * K2T];
__device__ float g_bsum[256];

__device__ __forceinline__ uint32_t smem_u32(const void* p) {
    uint32_t a;
    asm("{ .reg .u64 t; cvta.to.shared.u64 t, %1; cvt.u32.u64 %0, t; }" : "=r"(a) : "l"(p));
    return a;
}
__device__ __forceinline__ float tf32r(float f) {
    uint32_t u; asm("cvt.rna.tf32.f32 %0, %1;" : "=r"(u) : "f"(f));
    return __uint_as_float(u);
}
// per-32 chunk permutation (R5): k = ks*8 + c + 4*hi -> slot = 4*ks + c in float2 unit, hi = .y
__device__ __forceinline__ int kperm(int k) {
    const int ks = (k >> 3) & 3, c = k & 3, hi = (k >> 2) & 1;
    return (k & ~31) | ((4 * ks + c) * 2 + hi);
}
__device__ __forceinline__ void cpa16(uint32_t dst, const float* src, uint32_t sz) {
    asm volatile("cp.async.cg.shared.global [%0], [%1], 16, %2;" :: "r"(dst), "l"(src), "r"(sz));
}
#define CPA_COMMIT()  asm volatile("cp.async.commit_group;" ::: "memory")
#define CPA_WAIT1()   asm volatile("cp.async.wait_group 1;" ::: "memory")
#define CPA_WAIT0()   asm volatile("cp.async.wait_group 0;" ::: "memory")

__device__ __forceinline__ void mma8(float* d, uint32_t a0, uint32_t a1, uint32_t a2, uint32_t a3,
                                     uint32_t b0, uint32_t b1) {
    asm volatile("mma.sync.aligned.m16n8k8.row.col.f32.tf32.tf32.f32 "
                 "{%0,%1,%2,%3}, {%4,%5,%6,%7}, {%8,%9}, {%0,%1,%2,%3};"
                 : "+f"(d[0]), "+f"(d[1]), "+f"(d[2]), "+f"(d[3])
                 : "r"(a0), "r"(a1), "r"(a2), "r"(a3), "r"(b0), "r"(b1));
}

// As/Bs: 128 rows x 128B; float2 unit u stored at u ^ (4*(row&3)).
// Unit slot 4*ks+c holds (k=8ks+c, k=8ks+c+4). Warp tile 64x64: mi 0..3, ni 0..7.
__device__ __forceinline__ void compute_chunk(const char* As, const char* Bs,
                                              float acc[4][8][4], int lane, int wm, int wn)
{
    const int r = lane >> 2, c = lane & 3;
    const int swz = 4 * (r & 3);
    #pragma unroll
    for (int ks = 0; ks < 4; ks++) {
        const int u = ((4 * ks + c) ^ swz) * 8;
        float2 aL[4], aH[4];
        #pragma unroll
        for (int mi = 0; mi < 4; mi++) {
            const int row0 = wm * 64 + mi * 16 + r;
            aL[mi] = *(const float2*)(As + row0 * 128 + u);
            aH[mi] = *(const float2*)(As + (row0 + 8) * 128 + u);
        }
        #pragma unroll
        for (int ni = 0; ni < 8; ni++) {
            const float2 bv = *(const float2*)(Bs + (wn * 64 + ni * 8 + r) * 128 + u);
            #pragma unroll
            for (int mi = 0; mi < 4; mi++)
                mma8(acc[mi][ni], __float_as_uint(aL[mi].x), __float_as_uint(aH[mi].x),
                     __float_as_uint(aL[mi].y), __float_as_uint(aH[mi].y),
                     __float_as_uint(bv.x), __float_as_uint(bv.y));
        }
    }
}

// ---- prep ----
__global__ __launch_bounds__(256)
void k0a_w(const float* __restrict__ wy, const float* __restrict__ wl, const float* __restrict__ wp)
{
    const int co = blockIdx.x, t = threadIdx.x;
    __shared__ float red[256];
    float s = 0.f;
    for (int k = t; k < K1T; k += 256) {
        float v = wy[(size_t)k * 256 + co];
        s += v * v;
        g_wyT[(size_t)co * K1T + kperm(k)] = tf32r(v);
    }
    red[t] = s; __syncthreads();
    for (int o = 128; o > 0; o >>= 1) { if (t < o) red[t] += red[t + o]; __syncthreads(); }
    if (t == 0) g_bsum[co] = red[0];
    for (int k = t; k < K2T; k += 256) {
        float v = (k < 2304) ? wl[(size_t)k * 256 + co] : wp[(size_t)(k - 2304) * 256 + co];
        g_wlT[(size_t)co * K2T + kperm(k)] = tf32r(v);
    }
}
__global__ __launch_bounds__(256)
void k0b_x(const float* __restrict__ x)
{
    const int p = blockIdx.x * 8 + (threadIdx.x >> 5), lane = threadIdx.x & 31;
    float4 v = *(const float4*)(x + (size_t)p * 128 + lane * 4);
    float s = v.x * v.x + v.y * v.y + v.z * v.z + v.w * v.w;
    #pragma unroll
    for (int o = 16; o > 0; o >>= 1) s += __shfl_xor_sync(0xffffffff, s, o);
    if (lane == 0) g_sq[p] = s;
    float* dst = g_xr + (size_t)p * 128;
    const int ch = lane * 4;
    dst[kperm(ch)]     = tf32r(v.x);
    dst[kperm(ch + 1)] = tf32r(v.y);
    dst[kperm(ch + 2)] = tf32r(v.z);
    dst[kperm(ch + 3)] = tf32r(v.w);
}
__global__ __launch_bounds__(256)
void k0c_asum()
{
    const int p = blockIdx.x * 256 + threadIdx.x;
    const int h = (p >> 6) & 63, w = p & 63;
    float s = 0.f;
    #pragma unroll
    for (int dh = -1; dh <= 1; dh++)
        #pragma unroll
        for (int dw = -1; dw <= 1; dw++) {
            int hh = h + dh, ww = w + dw;
            if ((unsigned)hh < 64u && (unsigned)ww < 64u) s += g_sq[p + dh * 64 + dw];
        }
    g_asum[p] = s;
}

// ---- k1: yat conv. 128 threads, 4 warps of 64x64. ----
__global__ __launch_bounds__(128, 2)
void k1_yat(const float* __restrict__ alphap)
{
    extern __shared__ float smf[];
    const uint32_t sb = smem_u32(smf);
    const int tid = threadIdx.x, lane = tid & 31, wid = tid >> 5;
    const int wm = wid >> 1, wn = wid & 1;
    const int m_base = blockIdx.y * 128, c_base = blockIdx.x * 128;
    float* sbsum = smf + 24576;
    sbsum[tid] = g_bsum[c_base + tid];

    float acc[4][8][4];
    #pragma unroll
    for (int mi = 0; mi < 4; mi++)
        #pragma unroll
        for (int ni = 0; ni < 8; ni++)
            #pragma unroll
            for (int e = 0; e < 4; e++) acc[mi][ni][e] = 0.f;

    const int t8 = tid & 7, row0 = tid >> 3;   // unit 0..7, row 0..15
    auto stage = [&](int c, int b) {
        const int khw = c >> 2, c0 = (c & 3) * 32;
        const int dh = khw / 3 - 1, dw = khw % 3 - 1;
        const uint32_t base = sb + (uint32_t)b * 32768u;
        #pragma unroll
        for (int p = 0; p < 8; p++) {
            const int r = row0 + 16 * p, m = m_base + r;
            const int h = (m >> 6) & 63, w = m & 63;
            const int hh = h + dh, ww = w + dw;
            const bool ok = (unsigned)hh < 64u && (unsigned)ww < 64u;
            const uint32_t du = (uint32_t)(r * 128 + ((t8 ^ (2 * (r & 3))) * 16));
            const float* src = g_xr + (size_t)(m + dh * 64 + dw) * 128 + c0 + t8 * 4;
            cpa16(base + du, ok ? src : g_xr, ok ? 16u : 0u);
            cpa16(base + 16384u + du,
                  g_wyT + (size_t)(c_base + r) * K1T + c * 32 + t8 * 4, 16u);
        }
        CPA_COMMIT();
    };

    stage(0, 0); stage(1, 1);
    int b = 0;
    for (int c = 0; c < NCH1; c++) {
        if (c + 1 < NCH1) CPA_WAIT1(); else CPA_WAIT0();
        __syncthreads();
        if (c + 2 < NCH1) { int b2 = b + 2; if (b2 >= 3) b2 -= 3; stage(c + 2, b2); }
        compute_chunk((const char*)smf + b * 32768, (const char*)smf + b * 32768 + 16384,
                      acc, lane, wm, wn);
        if (++b == 3) b = 0;
    }

    const float scale = powf(16.f / log1pf(256.f), alphap[0]);
    #pragma unroll
    for (int mi = 0; mi < 4; mi++) {
        const int r0 = wm * 64 + mi * 16 + (lane >> 2);
        const int m0 = m_base + r0, m1 = m0 + 8;
        const float as0 = g_asum[m0], as1 = g_asum[m1];
        #pragma unroll
        for (int ni = 0; ni < 8; ni++) {
            const int cl = wn * 64 + ni * 8 + (lane & 3) * 2;
            const float bs0 = sbsum[cl], bs1 = sbsum[cl + 1];
            const float* d = acc[mi][ni];
            const float y00 = tf32r(d[0] * d[0] / (as0 + bs0 - 2.f * d[0] + 1e-5f) * scale);
            const float y01 = tf32r(d[1] * d[1] / (as0 + bs1 - 2.f * d[1] + 1e-5f) * scale);
            const float y10 = tf32r(d[2] * d[2] / (as1 + bs0 - 2.f * d[2] + 1e-5f) * scale);
            const float y11 = tf32r(d[3] * d[3] / (as1 + bs1 - 2.f * d[3] + 1e-5f) * scale);
            const int p0 = c_base + kperm(cl), p1 = c_base + kperm(cl + 1);
            g_y[(size_t)m0 * 256 + p0] = y00;
            g_y[(size_t)m0 * 256 + p1] = y01;
            g_y[(size_t)m1 * 256 + p0] = y10;
            g_y[(size_t)m1 * 256 + p1] = y11;
        }
    }
}

// ---- k2: lin conv + residual + 2x2 avg pool. 128 threads, 4 warps of 64x64. ----
__global__ __launch_bounds__(128, 2)
void k2_lin(float* __restrict__ out)
{
    extern __shared__ float smf[];
    const uint32_t sb = smem_u32(smf);
    const int tid = threadIdx.x, lane = tid & 31, wid = tid >> 5;
    const int wm = wid >> 1, wn = wid & 1;
    const int m_base = blockIdx.y * 128, c_base = blockIdx.x * 128;

    float acc[4][8][4];
    #pragma unroll
    for (int mi = 0; mi < 4; mi++)
        #pragma unroll
        for (int ni = 0; ni < 8; ni++)
            #pragma unroll
            for (int e = 0; e < 4; e++) acc[mi][ni][e] = 0.f;

    const int t8 = tid & 7, row0 = tid >> 3;
    auto stage = [&](int c, int b) {
        const uint32_t base = sb + (uint32_t)b * 32768u;
        if (c < 72) {
            const int khw = c >> 3, c0 = (c & 7) * 32;
            const int dh = khw / 3 - 1, dw = khw % 3 - 1;
            #pragma unroll
            for (int p = 0; p < 8; p++) {
                const int r = row0 + 16 * p, m = m_base + r;
                const int h = (m >> 6) & 63, w = m & 63;
                const int hh = h + dh, ww = w + dw;
                const bool ok = (unsigned)hh < 64u && (unsigned)ww < 64u;
                const uint32_t du = (uint32_t)(r * 128 + ((t8 ^ (2 * (r & 3))) * 16));
                const float* src = g_y + (size_t)(m + dh * 64 + dw) * 256 + c0 + t8 * 4;
                cpa16(base + du, ok ? src : g_y, ok ? 16u : 0u);
                cpa16(base + 16384u + du,
                      g_wlT + (size_t)(c_base + r) * K2T + c * 32 + t8 * 4, 16u);
            }
        } else {
            const int c0 = (c - 72) * 32;
            #pragma unroll
            for (int p = 0; p < 8; p++) {
                const int r = row0 + 16 * p;
                const uint32_t du = (uint32_t)(r * 128 + ((t8 ^ (2 * (r & 3))) * 16));
                cpa16(base + du, g_xr + (size_t)(m_base + r) * 128 + c0 + t8 * 4, 16u);
                cpa16(base + 16384u + du,
                      g_wlT + (size_t)(c_base + r) * K2T + c * 32 + t8 * 4, 16u);
            }
        }
        CPA_COMMIT();
    };

    stage(0, 0); stage(1, 1);
    int b = 0;
    for (int c = 0; c < NCH2; c++) {
        if (c + 1 < NCH2) CPA_WAIT1(); else CPA_WAIT0();
        __syncthreads();
        if (c + 2 < NCH2) { int b2 = b + 2; if (b2 >= 3) b2 -= 3; stage(c + 2, b2); }
        compute_chunk((const char*)smf + b * 32768, (const char*)smf + b * 32768 + 16384,
                      acc, lane, wm, wn);
        if (++b == 3) b = 0;
    }

    __syncthreads();
    #pragma unroll
    for (int mi = 0; mi < 4; mi++) {
        const int r0 = wm * 64 + mi * 16 + (lane >> 2);
        #pragma unroll
        for (int ni = 0; ni < 8; ni++) {
            const int cl = wn * 64 + ni * 8 + (lane & 3) * 2;
            const float* d = acc[mi][ni];
            *(float2*)(smf + r0 * 132 + cl) = make_float2(d[0], d[1]);
            *(float2*)(smf + (r0 + 8) * 132 + cl) = make_float2(d[2], d[3]);
        }
    }
    __syncthreads();
    const int n = m_base >> 12, hp = ((m_base >> 6) & 63) >> 1;
    #pragma unroll
    for (int it = 0; it < 8; it++) {
        const int idx = tid + it * 128, pw = idx >> 5, ch = (idx & 31) * 4;
        float4 a0 = *(const float4*)(smf + (2 * pw) * 132 + ch);
        float4 a1 = *(const float4*)(smf + (2 * pw + 1) * 132 + ch);
        float4 a2 = *(const float4*)(smf + (64 + 2 * pw) * 132 + ch);
        float4 a3 = *(const float4*)(smf + (64 + 2 * pw + 1) * 132 + ch);
        *(float4*)(out + ((size_t)((n * 32 + hp) * 32 + pw)) * 256 + c_base + ch) =
            make_float4(0.25f * (a0.x + a1.x + a2.x + a3.x), 0.25f * (a0.y + a1.y + a2.y + a3.y),
                        0.25f * (a0.z + a1.z + a2.z + a3.z), 0.25f * (a0.w + a1.w + a2.w + a3.w));
    }
}

extern "C" void kernel_launch(void* const* d_in, const int* in_sizes, int n_in,
                              void* d_out, int out_size)
{
    const float* x  = (const float*)d_in[0];
    const float* wy = (const float*)d_in[1];
    const float* al = (const float*)d_in[2];
    const float* wl = (const float*)d_in[3];
    const float* wp = (const float*)d_in[4];
    float* out = (float*)d_out;

    cudaFuncSetAttribute(k1_yat, cudaFuncAttributeMaxDynamicSharedMemorySize, 98816);
    cudaFuncSetAttribute(k2_lin, cudaFuncAttributeMaxDynamicSharedMemorySize, 98304);

    k0a_w<<<256, 256>>>(wy, wl, wp);
    k0b_x<<<16384, 256>>>(x);
    k0c_asum<<<512, 256>>>();
    k1_yat<<<dim3(2, 1024), 128, 98816>>>(al);
    k2_lin<<<dim3(2, 1024), 128, 98304>>>(out);
}

// round 8
// speedup vs baseline: 1.1307x; 1.0305x over previous
#include <cuda_runtime.h>
#include <cstdint>
#include <math.h>

#define K1T 1152
#define K2T 2432
#define NCH1 36
#define NCH2 76
#define PH 66                 // padded spatial dim
#define PIX (PH*PH)           // 4356 padded pixels per image

// Halo-padded intermediates: borders are never written and stay zero
// (CUDA zero-initializes __device__ globals).
__device__ float g_y[(size_t)32 * PIX * 256];    // ~143 MB
__device__ float g_xr[(size_t)32 * PIX * 128];   // ~71 MB
__device__ float g_sq[131072];
__device__ float g_asum[131072];
__device__ float g_wyT[256 * K1T];
__device__ float g_wlT[256 * K2T];
__device__ float g_bsum[256];

__device__ __forceinline__ uint32_t smem_u32(const void* p) {
    uint32_t a;
    asm("{ .reg .u64 t; cvta.to.shared.u64 t, %1; cvt.u32.u64 %0, t; }" : "=r"(a) : "l"(p));
    return a;
}
__device__ __forceinline__ float tf32r(float f) {
    uint32_t u; asm("cvt.rna.tf32.f32 %0, %1;" : "=r"(u) : "f"(f));
    return __uint_as_float(u);
}
// per-32 chunk permutation: k = ks*8 + c + 4*hi -> float2 slot 4*ks+c, hi = .y
__device__ __forceinline__ int kperm(int k) {
    const int ks = (k >> 3) & 3, c = k & 3, hi = (k >> 2) & 1;
    return (k & ~31) | ((4 * ks + c) * 2 + hi);
}
__device__ __forceinline__ void cpa16(uint32_t dst, const float* src) {
    asm volatile("cp.async.cg.shared.global [%0], [%1], 16;" :: "r"(dst), "l"(src));
}
#define CPA_COMMIT()  asm volatile("cp.async.commit_group;" ::: "memory")
#define CPA_WAIT1()   asm volatile("cp.async.wait_group 1;" ::: "memory")
#define CPA_WAIT0()   asm volatile("cp.async.wait_group 0;" ::: "memory")

__device__ __forceinline__ void mma8(float* d, uint32_t a0, uint32_t a1, uint32_t a2, uint32_t a3,
                                     uint32_t b0, uint32_t b1) {
    asm volatile("mma.sync.aligned.m16n8k8.row.col.f32.tf32.tf32.f32 "
                 "{%0,%1,%2,%3}, {%4,%5,%6,%7}, {%8,%9}, {%0,%1,%2,%3};"
                 : "+f"(d[0]), "+f"(d[1]), "+f"(d[2]), "+f"(d[3])
                 : "r"(a0), "r"(a1), "r"(a2), "r"(a3), "r"(b0), "r"(b1));
}

// As/Bs: 128 rows x 128B; float2 unit u stored at u ^ (4*(row&3)). Warp tile 64x64.
__device__ __forceinline__ void compute_chunk(const char* As, const char* Bs,
                                              float acc[4][8][4], int lane, int wm, int wn)
{
    const int r = lane >> 2, c = lane & 3;
    const int swz = 4 * (r & 3);
    #pragma unroll
    for (int ks = 0; ks < 4; ks++) {
        const int u = ((4 * ks + c) ^ swz) * 8;
        float2 aL[4], aH[4];
        #pragma unroll
        for (int mi = 0; mi < 4; mi++) {
            const int row0 = wm * 64 + mi * 16 + r;
            aL[mi] = *(const float2*)(As + row0 * 128 + u);
            aH[mi] = *(const float2*)(As + (row0 + 8) * 128 + u);
        }
        #pragma unroll
        for (int ni = 0; ni < 8; ni++) {
            const float2 bv = *(const float2*)(Bs + (wn * 64 + ni * 8 + r) * 128 + u);
            #pragma unroll
            for (int mi = 0; mi < 4; mi++)
                mma8(acc[mi][ni], __float_as_uint(aL[mi].x), __float_as_uint(aH[mi].x),
                     __float_as_uint(aL[mi].y), __float_as_uint(aH[mi].y),
                     __float_as_uint(bv.x), __float_as_uint(bv.y));
        }
    }
}

// padded pixel offset for dense m-index
__device__ __forceinline__ size_t padpix(int m) {
    const int n = m >> 12, h = (m >> 6) & 63, w = m & 63;
    return (size_t)((n * PH + h + 1) * PH + (w + 1));
}

// ---- prep ----
__global__ __launch_bounds__(256)
void k0a_w(const float* __restrict__ wy, const float* __restrict__ wl, const float* __restrict__ wp)
{
    const int co = blockIdx.x, t = threadIdx.x;
    __shared__ float red[256];
    float s = 0.f;
    for (int k = t; k < K1T; k += 256) {
        float v = wy[(size_t)k * 256 + co];
        s += v * v;
        g_wyT[(size_t)co * K1T + kperm(k)] = tf32r(v);
    }
    red[t] = s; __syncthreads();
    for (int o = 128; o > 0; o >>= 1) { if (t < o) red[t] += red[t + o]; __syncthreads(); }
    if (t == 0) g_bsum[co] = red[0];
    for (int k = t; k < K2T; k += 256) {
        float v = (k < 2304) ? wl[(size_t)k * 256 + co] : wp[(size_t)(k - 2304) * 256 + co];
        g_wlT[(size_t)co * K2T + kperm(k)] = tf32r(v);
    }
}
__global__ __launch_bounds__(256)
void k0b_x(const float* __restrict__ x)
{
    const int p = blockIdx.x * 8 + (threadIdx.x >> 5), lane = threadIdx.x & 31;
    float4 v = *(const float4*)(x + (size_t)p * 128 + lane * 4);
    float s = v.x * v.x + v.y * v.y + v.z * v.z + v.w * v.w;
    #pragma unroll
    for (int o = 16; o > 0; o >>= 1) s += __shfl_xor_sync(0xffffffff, s, o);
    if (lane == 0) g_sq[p] = s;
    float* dst = g_xr + padpix(p) * 128;
    const int ch = lane * 4;
    dst[kperm(ch)]     = tf32r(v.x);
    dst[kperm(ch + 1)] = tf32r(v.y);
    dst[kperm(ch + 2)] = tf32r(v.z);
    dst[kperm(ch + 3)] = tf32r(v.w);
}
__global__ __launch_bounds__(256)
void k0c_asum()
{
    const int p = blockIdx.x * 256 + threadIdx.x;
    const int h = (p >> 6) & 63, w = p & 63;
    float s = 0.f;
    #pragma unroll
    for (int dh = -1; dh <= 1; dh++)
        #pragma unroll
        for (int dw = -1; dw <= 1; dw++) {
            int hh = h + dh, ww = w + dw;
            if ((unsigned)hh < 64u && (unsigned)ww < 64u) s += g_sq[p + dh * 64 + dw];
        }
    g_asum[p] = s;
}

// ---- k1: yat conv. 128 threads, 4 warps of 64x64. ----
__global__ __launch_bounds__(128, 2)
void k1_yat(const float* __restrict__ alphap)
{
    extern __shared__ float smf[];
    const uint32_t sb = smem_u32(smf);
    const int tid = threadIdx.x, lane = tid & 31, wid = tid >> 5;
    const int wm = wid >> 1, wn = wid & 1;
    const int m_base = blockIdx.y * 128, c_base = blockIdx.x * 128;
    float* sbsum = smf + 24576;
    sbsum[tid] = g_bsum[c_base + tid];

    float acc[4][8][4];
    #pragma unroll
    for (int mi = 0; mi < 4; mi++)
        #pragma unroll
        for (int ni = 0; ni < 8; ni++)
            #pragma unroll
            for (int e = 0; e < 4; e++) acc[mi][ni][e] = 0.f;

    const int t8 = tid & 7, row0 = tid >> 3;
    // hoisted staging state: 8 spatial base pointers, affine weight/smem bases
    const float* xb[8];
    #pragma unroll
    for (int p = 0; p < 8; p++)
        xb[p] = g_xr + padpix(m_base + row0 + 16 * p) * 128 + t8 * 4;
    const float* wb0 = g_wyT + (size_t)(c_base + row0) * K1T + t8 * 4;
    const uint32_t du0 = (uint32_t)(row0 * 128 + ((t8 ^ (2 * (row0 & 3))) * 16));

    auto stage = [&](int c, int b) {
        const int khw = c >> 2, c0 = (c & 3) * 32;
        const int dh = khw / 3 - 1, dw = khw % 3 - 1;
        const int xoff = (dh * PH + dw) * 128 + c0;
        const uint32_t base = sb + (uint32_t)b * 32768u + du0;
        const float* wsrc = wb0 + c * 32;
        #pragma unroll
        for (int p = 0; p < 8; p++) {
            cpa16(base + p * 2048u, xb[p] + xoff);
            cpa16(base + 16384u + p * 2048u, wsrc + p * (16 * K1T));
        }
        CPA_COMMIT();
    };

    stage(0, 0); stage(1, 1);
    int b = 0;
    for (int c = 0; c < NCH1; c++) {
        if (c + 1 < NCH1) CPA_WAIT1(); else CPA_WAIT0();
        __syncthreads();
        if (c + 2 < NCH1) { int b2 = b + 2; if (b2 >= 3) b2 -= 3; stage(c + 2, b2); }
        compute_chunk((const char*)smf + b * 32768, (const char*)smf + b * 32768 + 16384,
                      acc, lane, wm, wn);
        if (++b == 3) b = 0;
    }

    const float scale = powf(16.f / log1pf(256.f), alphap[0]);
    #pragma unroll
    for (int mi = 0; mi < 4; mi++) {
        const int r0 = wm * 64 + mi * 16 + (lane >> 2);
        const int m0 = m_base + r0, m1 = m0 + 8;
        const float as0 = g_asum[m0], as1 = g_asum[m1];
        float* y0 = g_y + padpix(m0) * 256 + c_base;
        float* y1 = g_y + padpix(m1) * 256 + c_base;
        #pragma unroll
        for (int ni = 0; ni < 8; ni++) {
            const int cl = wn * 64 + ni * 8 + (lane & 3) * 2;
            const float bs0 = sbsum[cl], bs1 = sbsum[cl + 1];
            const float* d = acc[mi][ni];
            const int p0 = kperm(cl), p1 = kperm(cl + 1);
            y0[p0] = tf32r(d[0] * d[0] / (as0 + bs0 - 2.f * d[0] + 1e-5f) * scale);
            y0[p1] = tf32r(d[1] * d[1] / (as0 + bs1 - 2.f * d[1] + 1e-5f) * scale);
            y1[p0] = tf32r(d[2] * d[2] / (as1 + bs0 - 2.f * d[2] + 1e-5f) * scale);
            y1[p1] = tf32r(d[3] * d[3] / (as1 + bs1 - 2.f * d[3] + 1e-5f) * scale);
        }
    }
}

// ---- k2: lin conv + residual + 2x2 avg pool. 128 threads, 4 warps of 64x64. ----
__global__ __launch_bounds__(128, 2)
void k2_lin(float* __restrict__ out)
{
    extern __shared__ float smf[];
    const uint32_t sb = smem_u32(smf);
    const int tid = threadIdx.x, lane = tid & 31, wid = tid >> 5;
    const int wm = wid >> 1, wn = wid & 1;
    const int m_base = blockIdx.y * 128, c_base = blockIdx.x * 128;

    float acc[4][8][4];
    #pragma unroll
    for (int mi = 0; mi < 4; mi++)
        #pragma unroll
        for (int ni = 0; ni < 8; ni++)
            #pragma unroll
            for (int e = 0; e < 4; e++) acc[mi][ni][e] = 0.f;

    const int t8 = tid & 7, row0 = tid >> 3;
    const float* yb[8];
    #pragma unroll
    for (int p = 0; p < 8; p++)
        yb[p] = g_y + padpix(m_base + row0 + 16 * p) * 256 + t8 * 4;
    const float* wb0 = g_wlT + (size_t)(c_base + row0) * K2T + t8 * 4;
    const uint32_t du0 = (uint32_t)(row0 * 128 + ((t8 ^ (2 * (row0 & 3))) * 16));

    auto stage = [&](int c, int b) {
        const uint32_t base = sb + (uint32_t)b * 32768u + du0;
        const float* wsrc = wb0 + c * 32;
        if (c < 72) {
            const int khw = c >> 3, c0 = (c & 7) * 32;
            const int dh = khw / 3 - 1, dw = khw % 3 - 1;
            const int yoff = (dh * PH + dw) * 256 + c0;
            #pragma unroll
            for (int p = 0; p < 8; p++) {
                cpa16(base + p * 2048u, yb[p] + yoff);
                cpa16(base + 16384u + p * 2048u, wsrc + p * (16 * K2T));
            }
        } else {
            const int c0 = (c - 72) * 32;
            #pragma unroll
            for (int p = 0; p < 8; p++) {
                const float* xs = g_xr + padpix(m_base + row0 + 16 * p) * 128 + c0 + t8 * 4;
                cpa16(base + p * 2048u, xs);
                cpa16(base + 16384u + p * 2048u, wsrc + p * (16 * K2T));
            }
        }
        CPA_COMMIT();
    };

    stage(0, 0); stage(1, 1);
    int b = 0;
    for (int c = 0; c < NCH2; c++) {
        if (c + 1 < NCH2) CPA_WAIT1(); else CPA_WAIT0();
        __syncthreads();
        if (c + 2 < NCH2) { int b2 = b + 2; if (b2 >= 3) b2 -= 3; stage(c + 2, b2); }
        compute_chunk((const char*)smf + b * 32768, (const char*)smf + b * 32768 + 16384,
                      acc, lane, wm, wn);
        if (++b == 3) b = 0;
    }

    __syncthreads();
    #pragma unroll
    for (int mi = 0; mi < 4; mi++) {
        const int r0 = wm * 64 + mi * 16 + (lane >> 2);
        #pragma unroll
        for (int ni = 0; ni < 8; ni++) {
            const int cl = wn * 64 + ni * 8 + (lane & 3) * 2;
            const float* d = acc[mi][ni];
            *(float2*)(smf + r0 * 132 + cl) = make_float2(d[0], d[1]);
            *(float2*)(smf + (r0 + 8) * 132 + cl) = make_float2(d[2], d[3]);
        }
    }
    __syncthreads();
    const int n = m_base >> 12, hp = ((m_base >> 6) & 63) >> 1;
    #pragma unroll
    for (int it = 0; it < 8; it++) {
        const int idx = tid + it * 128, pw = idx >> 5, ch = (idx & 31) * 4;
        float4 a0 = *(const float4*)(smf + (2 * pw) * 132 + ch);
        float4 a1 = *(const float4*)(smf + (2 * pw + 1) * 132 + ch);
        float4 a2 = *(const float4*)(smf + (64 + 2 * pw) * 132 + ch);
        float4 a3 = *(const float4*)(smf + (64 + 2 * pw + 1) * 132 + ch);
        *(float4*)(out + ((size_t)((n * 32 + hp) * 32 + pw)) * 256 + c_base + ch) =
            make_float4(0.25f * (a0.x + a1.x + a2.x + a3.x), 0.25f * (a0.y + a1.y + a2.y + a3.y),
                        0.25f * (a0.z + a1.z + a2.z + a3.z), 0.25f * (a0.w + a1.w + a2.w + a3.w));
    }
}

extern "C" void kernel_launch(void* const* d_in, const int* in_sizes, int n_in,
                              void* d_out, int out_size)
{
    const float* x  = (const float*)d_in[0];
    const float* wy = (const float*)d_in[1];
    const float* al = (const float*)d_in[2];
    const float* wl = (const float*)d_in[3];
    const float* wp = (const float*)d_in[4];
    float* out = (float*)d_out;

    cudaFuncSetAttribute(k1_yat, cudaFuncAttributeMaxDynamicSharedMemorySize, 98816);
    cudaFuncSetAttribute(k2_lin, cudaFuncAttributeMaxDynamicSharedMemorySize, 98304);

    k0a_w<<<256, 256>>>(wy, wl, wp);
    k0b_x<<<16384, 256>>>(x);
    k0c_asum<<<512, 256>>>();
    k1_yat<<<dim3(2, 1024), 128, 98816>>>(al);
    k2_lin<<<dim3(2, 1024), 128, 98304>>>(out);
}

// round 9
// speedup vs baseline: 1.2609x; 1.1151x over previous
#include <cuda_runtime.h>
#include <cstdint>
#include <math.h>

#define K1T 1152
#define K2T 2432
#define NCH1 36
#define NCH2 76
#define PH 66
#define PIX (PH*PH)

__device__ float g_y[(size_t)32 * PIX * 256];
__device__ float g_xr[(size_t)32 * PIX * 128];
__device__ float g_sq[131072];
__device__ float g_asum[131072];
__device__ float g_wyT[256 * K1T];
__device__ float g_wlT[256 * K2T];
__device__ float g_bsum[256];

__device__ __forceinline__ uint32_t smem_u32(const void* p) {
    uint32_t a;
    asm("{ .reg .u64 t; cvta.to.shared.u64 t, %1; cvt.u32.u64 %0, t; }" : "=r"(a) : "l"(p));
    return a;
}
__device__ __forceinline__ float tf32r(float f) {
    uint32_t u; asm("cvt.rna.tf32.f32 %0, %1;" : "=r"(u) : "f"(f));
    return __uint_as_float(u);
}
__device__ __forceinline__ int kperm(int k) {
    const int ks = (k >> 3) & 3, c = k & 3, hi = (k >> 2) & 1;
    return (k & ~31) | ((4 * ks + c) * 2 + hi);
}
__device__ __forceinline__ void cpa16(uint32_t dst, const float* src) {
    asm volatile("cp.async.cg.shared.global [%0], [%1], 16;" :: "r"(dst), "l"(src));
}
#define CPA_COMMIT()  asm volatile("cp.async.commit_group;" ::: "memory")
#define CPA_WAIT1()   asm volatile("cp.async.wait_group 1;" ::: "memory")
#define CPA_WAIT0()   asm volatile("cp.async.wait_group 0;" ::: "memory")

__device__ __forceinline__ void mma8(float* d, uint32_t a0, uint32_t a1, uint32_t a2, uint32_t a3,
                                     uint32_t b0, uint32_t b1) {
    asm volatile("mma.sync.aligned.m16n8k8.row.col.f32.tf32.tf32.f32 "
                 "{%0,%1,%2,%3}, {%4,%5,%6,%7}, {%8,%9}, {%0,%1,%2,%3};"
                 : "+f"(d[0]), "+f"(d[1]), "+f"(d[2]), "+f"(d[3])
                 : "r"(a0), "r"(a1), "r"(a2), "r"(a3), "r"(b0), "r"(b1));
}

// Fragment load for one ks step: 8 A float2 + 8 B float2.
__device__ __forceinline__ void ldfrag(const char* As, const char* Bs, int ks, int lane,
                                       int wm, int wn, float2* aL, float2* aH, float2* bv)
{
    const int r = lane >> 2, c = lane & 3;
    const int u = ((4 * ks + c) ^ (4 * (r & 3))) * 8;
    #pragma unroll
    for (int mi = 0; mi < 4; mi++) {
        const int row0 = wm * 64 + mi * 16 + r;
        aL[mi] = *(const float2*)(As + row0 * 128 + u);
        aH[mi] = *(const float2*)(As + (row0 + 8) * 128 + u);
    }
    #pragma unroll
    for (int ni = 0; ni < 8; ni++)
        bv[ni] = *(const float2*)(Bs + (wn * 64 + ni * 8 + r) * 128 + u);
}
__device__ __forceinline__ void do_mmas(float acc[4][8][4], const float2* aL, const float2* aH,
                                        const float2* bv)
{
    #pragma unroll
    for (int ni = 0; ni < 8; ni++)
        #pragma unroll
        for (int mi = 0; mi < 4; mi++)
            mma8(acc[mi][ni], __float_as_uint(aL[mi].x), __float_as_uint(aH[mi].x),
                 __float_as_uint(aL[mi].y), __float_as_uint(aH[mi].y),
                 __float_as_uint(bv[ni].x), __float_as_uint(bv[ni].y));
}
// 2-deep software-pipelined chunk: load ks+1 fragments before issuing ks MMAs.
__device__ __forceinline__ void compute_chunk(const char* As, const char* Bs,
                                              float acc[4][8][4], int lane, int wm, int wn)
{
    float2 aL[2][4], aH[2][4], bv[2][8];
    ldfrag(As, Bs, 0, lane, wm, wn, aL[0], aH[0], bv[0]);
    #pragma unroll
    for (int ks = 0; ks < 4; ks++) {
        if (ks < 3) ldfrag(As, Bs, ks + 1, lane, wm, wn, aL[(ks + 1) & 1], aH[(ks + 1) & 1], bv[(ks + 1) & 1]);
        do_mmas(acc, aL[ks & 1], aH[ks & 1], bv[ks & 1]);
    }
}

__device__ __forceinline__ size_t padpix(int m) {
    const int n = m >> 12, h = (m >> 6) & 63, w = m & 63;
    return (size_t)((n * PH + h + 1) * PH + (w + 1));
}

// ---- prep ----
__global__ __launch_bounds__(256)
void k0a_w(const float* __restrict__ wy, const float* __restrict__ wl, const float* __restrict__ wp)
{
    const int co = blockIdx.x, t = threadIdx.x;
    __shared__ float red[256];
    float s = 0.f;
    for (int k = t; k < K1T; k += 256) {
        float v = wy[(size_t)k * 256 + co];
        s += v * v;
        g_wyT[(size_t)co * K1T + kperm(k)] = tf32r(v);
    }
    red[t] = s; __syncthreads();
    for (int o = 128; o > 0; o >>= 1) { if (t < o) red[t] += red[t + o]; __syncthreads(); }
    if (t == 0) g_bsum[co] = red[0];
    for (int k = t; k < K2T; k += 256) {
        float v = (k < 2304) ? wl[(size_t)k * 256 + co] : wp[(size_t)(k - 2304) * 256 + co];
        g_wlT[(size_t)co * K2T + kperm(k)] = tf32r(v);
    }
}
__global__ __launch_bounds__(256)
void k0b_x(const float* __restrict__ x)
{
    const int p = blockIdx.x * 8 + (threadIdx.x >> 5), lane = threadIdx.x & 31;
    float4 v = *(const float4*)(x + (size_t)p * 128 + lane * 4);
    float s = v.x * v.x + v.y * v.y + v.z * v.z + v.w * v.w;
    #pragma unroll
    for (int o = 16; o > 0; o >>= 1) s += __shfl_xor_sync(0xffffffff, s, o);
    if (lane == 0) g_sq[p] = s;
    float* dst = g_xr + padpix(p) * 128;
    const int ch = lane * 4;
    dst[kperm(ch)]     = tf32r(v.x);
    dst[kperm(ch + 1)] = tf32r(v.y);
    dst[kperm(ch + 2)] = tf32r(v.z);
    dst[kperm(ch + 3)] = tf32r(v.w);
}
__global__ __launch_bounds__(256)
void k0c_asum()
{
    const int p = blockIdx.x * 256 + threadIdx.x;
    const int h = (p >> 6) & 63, w = p & 63;
    float s = 0.f;
    #pragma unroll
    for (int dh = -1; dh <= 1; dh++)
        #pragma unroll
        for (int dw = -1; dw <= 1; dw++) {
            int hh = h + dh, ww = w + dw;
            if ((unsigned)hh < 64u && (unsigned)ww < 64u) s += g_sq[p + dh * 64 + dw];
        }
    g_asum[p] = s;
}

// ---- k1 ----
__global__ __launch_bounds__(128, 2)
void k1_yat(const float* __restrict__ alphap)
{
    extern __shared__ float smf[];
    const uint32_t sb = smem_u32(smf);
    const int tid = threadIdx.x, lane = tid & 31, wid = tid >> 5;
    const int wm = wid >> 1, wn = wid & 1;
    const int m_base = blockIdx.y * 128, c_base = blockIdx.x * 128;
    float* sbsum = smf + 24576;
    sbsum[tid] = g_bsum[c_base + tid];

    float acc[4][8][4];
    #pragma unroll
    for (int mi = 0; mi < 4; mi++)
        #pragma unroll
        for (int ni = 0; ni < 8; ni++)
            #pragma unroll
            for (int e = 0; e < 4; e++) acc[mi][ni][e] = 0.f;

    const int t8 = tid & 7, row0 = tid >> 3;
    const float* xb[8];
    #pragma unroll
    for (int p = 0; p < 8; p++)
        xb[p] = g_xr + padpix(m_base + row0 + 16 * p) * 128 + t8 * 4;
    const float* wb0 = g_wyT + (size_t)(c_base + row0) * K1T + t8 * 4;
    const uint32_t du0 = (uint32_t)(row0 * 128 + ((t8 ^ (2 * (row0 & 3))) * 16));

    auto stage = [&](int c, int b) {
        const int khw = c >> 2, c0 = (c & 3) * 32;
        const int dh = khw / 3 - 1, dw = khw % 3 - 1;
        const int xoff = (dh * PH + dw) * 128 + c0;
        const uint32_t base = sb + (uint32_t)b * 32768u + du0;
        const float* wsrc = wb0 + c * 32;
        #pragma unroll
        for (int p = 0; p < 8; p++) {
            cpa16(base + p * 2048u, xb[p] + xoff);
            cpa16(base + 16384u + p * 2048u, wsrc + p * (16 * K1T));
        }
        CPA_COMMIT();
    };

    stage(0, 0); stage(1, 1);
    int b = 0;
    for (int c = 0; c < NCH1; c++) {
        if (c + 1 < NCH1) CPA_WAIT1(); else CPA_WAIT0();
        __syncthreads();
        if (c + 2 < NCH1) { int b2 = b + 2; if (b2 >= 3) b2 -= 3; stage(c + 2, b2); }
        compute_chunk((const char*)smf + b * 32768, (const char*)smf + b * 32768 + 16384,
                      acc, lane, wm, wn);
        if (++b == 3) b = 0;
    }

    const float scale = powf(16.f / log1pf(256.f), alphap[0]);
    #pragma unroll
    for (int mi = 0; mi < 4; mi++) {
        const int r0 = wm * 64 + mi * 16 + (lane >> 2);
        const int m0 = m_base + r0, m1 = m0 + 8;
        const float as0 = g_asum[m0], as1 = g_asum[m1];
        float* y0 = g_y + padpix(m0) * 256 + c_base;
        float* y1 = g_y + padpix(m1) * 256 + c_base;
        #pragma unroll
        for (int ni = 0; ni < 8; ni++) {
            const int cl = wn * 64 + ni * 8 + (lane & 3) * 2;
            const float bs0 = sbsum[cl], bs1 = sbsum[cl + 1];
            const float* d = acc[mi][ni];
            const int p0 = kperm(cl), p1 = kperm(cl + 1);
            y0[p0] = tf32r(d[0] * d[0] / (as0 + bs0 - 2.f * d[0] + 1e-5f) * scale);
            y0[p1] = tf32r(d[1] * d[1] / (as0 + bs1 - 2.f * d[1] + 1e-5f) * scale);
            y1[p0] = tf32r(d[2] * d[2] / (as1 + bs0 - 2.f * d[2] + 1e-5f) * scale);
            y1[p1] = tf32r(d[3] * d[3] / (as1 + bs1 - 2.f * d[3] + 1e-5f) * scale);
        }
    }
}

// ---- k2 ----
__global__ __launch_bounds__(128, 2)
void k2_lin(float* __restrict__ out)
{
    extern __shared__ float smf[];
    const uint32_t sb = smem_u32(smf);
    const int tid = threadIdx.x, lane = tid & 31, wid = tid >> 5;
    const int wm = wid >> 1, wn = wid & 1;
    const int m_base = blockIdx.y * 128, c_base = blockIdx.x * 128;

    float acc[4][8][4];
    #pragma unroll
    for (int mi = 0; mi < 4; mi++)
        #pragma unroll
        for (int ni = 0; ni < 8; ni++)
            #pragma unroll
            for (int e = 0; e < 4; e++) acc[mi][ni][e] = 0.f;

    const int t8 = tid & 7, row0 = tid >> 3;
    const float *yb[8], *xb2[8];
    #pragma unroll
    for (int p = 0; p < 8; p++) {
        const size_t pp = padpix(m_base + row0 + 16 * p);
        yb[p]  = g_y  + pp * 256 + t8 * 4;
        xb2[p] = g_xr + pp * 128 + t8 * 4;
    }
    const float* wb0 = g_wlT + (size_t)(c_base + row0) * K2T + t8 * 4;
    const uint32_t du0 = (uint32_t)(row0 * 128 + ((t8 ^ (2 * (row0 & 3))) * 16));

    auto stage = [&](int c, int b) {
        const uint32_t base = sb + (uint32_t)b * 32768u + du0;
        const float* wsrc = wb0 + c * 32;
        if (c < 72) {
            const int khw = c >> 3, c0 = (c & 7) * 32;
            const int dh = khw / 3 - 1, dw = khw % 3 - 1;
            const int yoff = (dh * PH + dw) * 256 + c0;
            #pragma unroll
            for (int p = 0; p < 8; p++) {
                cpa16(base + p * 2048u, yb[p] + yoff);
                cpa16(base + 16384u + p * 2048u, wsrc + p * (16 * K2T));
            }
        } else {
            const int c0 = (c - 72) * 32;
            #pragma unroll
            for (int p = 0; p < 8; p++) {
                cpa16(base + p * 2048u, xb2[p] + c0);
                cpa16(base + 16384u + p * 2048u, wsrc + p * (16 * K2T));
            }
        }
        CPA_COMMIT();
    };

    stage(0, 0); stage(1, 1);
    int b = 0;
    for (int c = 0; c < NCH2; c++) {
        if (c + 1 < NCH2) CPA_WAIT1(); else CPA_WAIT0();
        __syncthreads();
        if (c + 2 < NCH2) { int b2 = b + 2; if (b2 >= 3) b2 -= 3; stage(c + 2, b2); }
        compute_chunk((const char*)smf + b * 32768, (const char*)smf + b * 32768 + 16384,
                      acc, lane, wm, wn);
        if (++b == 3) b = 0;
    }

    __syncthreads();
    #pragma unroll
    for (int mi = 0; mi < 4; mi++) {
        const int r0 = wm * 64 + mi * 16 + (lane >> 2);
        #pragma unroll
        for (int ni = 0; ni < 8; ni++) {
            const int cl = wn * 64 + ni * 8 + (lane & 3) * 2;
            const float* d = acc[mi][ni];
            *(float2*)(smf + r0 * 132 + cl) = make_float2(d[0], d[1]);
            *(float2*)(smf + (r0 + 8) * 132 + cl) = make_float2(d[2], d[3]);
        }
    }
    __syncthreads();
    const int n = m_base >> 12, hp = ((m_base >> 6) & 63) >> 1;
    #pragma unroll
    for (int it = 0; it < 8; it++) {
        const int idx = tid + it * 128, pw = idx >> 5, ch = (idx & 31) * 4;
        float4 a0 = *(const float4*)(smf + (2 * pw) * 132 + ch);
        float4 a1 = *(const float4*)(smf + (2 * pw + 1) * 132 + ch);
        float4 a2 = *(const float4*)(smf + (64 + 2 * pw) * 132 + ch);
        float4 a3 = *(const float4*)(smf + (64 + 2 * pw + 1) * 132 + ch);
        *(float4*)(out + ((size_t)((n * 32 + hp) * 32 + pw)) * 256 + c_base + ch) =
            make_float4(0.25f * (a0.x + a1.x + a2.x + a3.x), 0.25f * (a0.y + a1.y + a2.y + a3.y),
                        0.25f * (a0.z + a1.z + a2.z + a3.z), 0.25f * (a0.w + a1.w + a2.w + a3.w));
    }
}

extern "C" void kernel_launch(void* const* d_in, const int* in_sizes, int n_in,
                              void* d_out, int out_size)
{
    const float* x  = (const float*)d_in[0];
    const float* wy = (const float*)d_in[1];
    const float* al = (const float*)d_in[2];
    const float* wl = (const float*)d_in[3];
    const float* wp = (const float*)d_in[4];
    float* out = (float*)d_out;

    cudaFuncSetAttribute(k1_yat, cudaFuncAttributeMaxDynamicSharedMemorySize, 98816);
    cudaFuncSetAttribute(k2_lin, cudaFuncAttributeMaxDynamicSharedMemorySize, 98304);

    k0a_w<<<256, 256>>>(wy, wl, wp);
    k0b_x<<<16384, 256>>>(x);
    k0c_asum<<<512, 256>>>();
    k1_yat<<<dim3(2, 1024), 128, 98816>>>(al);
    k2_lin<<<dim3(2, 1024), 128, 98304>>>(out);
}

// round 10
// speedup vs baseline: 1.2883x; 1.0217x over previous
#include <cuda_runtime.h>
#include <cstdint>
#include <math.h>

#define K1T 1152
#define K2T 2432
#define NCH1 36
#define NCH2 76
#define PH 66
#define PIX (PH*PH)

__device__ float g_y[(size_t)32 * PIX * 256];
__device__ float g_xr[(size_t)32 * PIX * 128];
__device__ float g_sq[131072];
__device__ float g_asum[131072];
__device__ float g_wyT[256 * K1T];
__device__ float g_wlT[256 * K2T];
__device__ float g_bsum[256];

__device__ __forceinline__ uint32_t smem_u32(const void* p) {
    uint32_t a;
    asm("{ .reg .u64 t; cvta.to.shared.u64 t, %1; cvt.u32.u64 %0, t; }" : "=r"(a) : "l"(p));
    return a;
}
__device__ __forceinline__ float tf32r(float f) {
    uint32_t u; asm("cvt.rna.tf32.f32 %0, %1;" : "=r"(u) : "f"(f));
    return __uint_as_float(u);
}
__device__ __forceinline__ int kperm(int k) {
    const int ks = (k >> 3) & 3, c = k & 3, hi = (k >> 2) & 1;
    return (k & ~31) | ((4 * ks + c) * 2 + hi);
}
__device__ __forceinline__ void cpa16(uint32_t dst, const float* src) {
    asm volatile("cp.async.cg.shared.global [%0], [%1], 16;" :: "r"(dst), "l"(src));
}
#define CPA_COMMIT()  asm volatile("cp.async.commit_group;" ::: "memory")
#define CPA_WAIT1()   asm volatile("cp.async.wait_group 1;" ::: "memory")
#define CPA_WAIT0()   asm volatile("cp.async.wait_group 0;" ::: "memory")

__device__ __forceinline__ void mma8(float* d, uint32_t a0, uint32_t a1, uint32_t a2, uint32_t a3,
                                     uint32_t b0, uint32_t b1) {
    asm volatile("mma.sync.aligned.m16n8k8.row.col.f32.tf32.tf32.f32 "
                 "{%0,%1,%2,%3}, {%4,%5,%6,%7}, {%8,%9}, {%0,%1,%2,%3};"
                 : "+f"(d[0]), "+f"(d[1]), "+f"(d[2]), "+f"(d[3])
                 : "r"(a0), "r"(a1), "r"(a2), "r"(a3), "r"(b0), "r"(b1));
}

// Fragment load for one ks step: 8 A float2 + 8 B float2.
__device__ __forceinline__ void ldfrag(const char* As, const char* Bs, int ks, int lane,
                                       int wm, int wn, float2* aL, float2* aH, float2* bv)
{
    const int r = lane >> 2, c = lane & 3;
    const int u = ((4 * ks + c) ^ (4 * (r & 3))) * 8;
    #pragma unroll
    for (int mi = 0; mi < 4; mi++) {
        const int row0 = wm * 64 + mi * 16 + r;
        aL[mi] = *(const float2*)(As + row0 * 128 + u);
        aH[mi] = *(const float2*)(As + (row0 + 8) * 128 + u);
    }
    #pragma unroll
    for (int ni = 0; ni < 8; ni++)
        bv[ni] = *(const float2*)(Bs + (wn * 64 + ni * 8 + r) * 128 + u);
}
__device__ __forceinline__ void do_mmas(float acc[4][8][4], const float2* aL, const float2* aH,
                                        const float2* bv)
{
    #pragma unroll
    for (int ni = 0; ni < 8; ni++)
        #pragma unroll
        for (int mi = 0; mi < 4; mi++)
            mma8(acc[mi][ni], __float_as_uint(aL[mi].x), __float_as_uint(aH[mi].x),
                 __float_as_uint(aL[mi].y), __float_as_uint(aH[mi].y),
                 __float_as_uint(bv[ni].x), __float_as_uint(bv[ni].y));
}

__device__ __forceinline__ size_t padpix(int m) {
    const int n = m >> 12, h = (m >> 6) & 63, w = m & 63;
    return (size_t)((n * PH + h + 1) * PH + (w + 1));
}

// ---- prep ----
__global__ __launch_bounds__(256)
void k0a_w(const float* __restrict__ wy, const float* __restrict__ wl, const float* __restrict__ wp)
{
    const int co = blockIdx.x, t = threadIdx.x;
    __shared__ float red[256];
    float s = 0.f;
    for (int k = t; k < K1T; k += 256) {
        float v = wy[(size_t)k * 256 + co];
        s += v * v;
        g_wyT[(size_t)co * K1T + kperm(k)] = tf32r(v);
    }
    red[t] = s; __syncthreads();
    for (int o = 128; o > 0; o >>= 1) { if (t < o) red[t] += red[t + o]; __syncthreads(); }
    if (t == 0) g_bsum[co] = red[0];
    for (int k = t; k < K2T; k += 256) {
        float v = (k < 2304) ? wl[(size_t)k * 256 + co] : wp[(size_t)(k - 2304) * 256 + co];
        g_wlT[(size_t)co * K2T + kperm(k)] = tf32r(v);
    }
}
__global__ __launch_bounds__(256)
void k0b_x(const float* __restrict__ x)
{
    const int p = blockIdx.x * 8 + (threadIdx.x >> 5), lane = threadIdx.x & 31;
    float4 v = *(const float4*)(x + (size_t)p * 128 + lane * 4);
    float s = v.x * v.x + v.y * v.y + v.z * v.z + v.w * v.w;
    #pragma unroll
    for (int o = 16; o > 0; o >>= 1) s += __shfl_xor_sync(0xffffffff, s, o);
    if (lane == 0) g_sq[p] = s;
    float* dst = g_xr + padpix(p) * 128;
    const int ch = lane * 4;
    dst[kperm(ch)]     = tf32r(v.x);
    dst[kperm(ch + 1)] = tf32r(v.y);
    dst[kperm(ch + 2)] = tf32r(v.z);
    dst[kperm(ch + 3)] = tf32r(v.w);
}
__global__ __launch_bounds__(256)
void k0c_asum()
{
    const int p = blockIdx.x * 256 + threadIdx.x;
    const int h = (p >> 6) & 63, w = p & 63;
    float s = 0.f;
    #pragma unroll
    for (int dh = -1; dh <= 1; dh++)
        #pragma unroll
        for (int dw = -1; dw <= 1; dw++) {
            int hh = h + dh, ww = w + dw;
            if ((unsigned)hh < 64u && (unsigned)ww < 64u) s += g_sq[p + dh * 64 + dw];
        }
    g_asum[p] = s;
}

// ---- k1 ----
__global__ __launch_bounds__(128, 2)
void k1_yat(const float* __restrict__ alphap)
{
    extern __shared__ float smf[];
    const uint32_t sb = smem_u32(smf);
    const int tid = threadIdx.x, lane = tid & 31, wid = tid >> 5;
    const int wm = wid >> 1, wn = wid & 1;
    const int m_base = blockIdx.y * 128, c_base = blockIdx.x * 128;
    float* sbsum = smf + 24576;
    sbsum[tid] = g_bsum[c_base + tid];

    float acc[4][8][4];
    #pragma unroll
    for (int mi = 0; mi < 4; mi++)
        #pragma unroll
        for (int ni = 0; ni < 8; ni++)
            #pragma unroll
            for (int e = 0; e < 4; e++) acc[mi][ni][e] = 0.f;

    const int t8 = tid & 7, row0 = tid >> 3;
    const float* xb[8];
    #pragma unroll
    for (int p = 0; p < 8; p++)
        xb[p] = g_xr + padpix(m_base + row0 + 16 * p) * 128 + t8 * 4;
    const float* wb0 = g_wyT + (size_t)(c_base + row0) * K1T + t8 * 4;
    const uint32_t du0 = (uint32_t)(row0 * 128 + ((t8 ^ (2 * (row0 & 3))) * 16));

    auto stage = [&](int c, int b) {
        const int khw = c >> 2, c0 = (c & 3) * 32;
        const int dh = khw / 3 - 1, dw = khw % 3 - 1;
        const int xoff = (dh * PH + dw) * 128 + c0;
        const uint32_t base = sb + (uint32_t)b * 32768u + du0;
        const float* wsrc = wb0 + c * 32;
        #pragma unroll
        for (int p = 0; p < 8; p++) {
            cpa16(base + p * 2048u, xb[p] + xoff);
            cpa16(base + 16384u + p * 2048u, wsrc + p * (16 * K1T));
        }
        CPA_COMMIT();
    };

    stage(0, 0); stage(1, 1);
    CPA_WAIT1(); __syncthreads();
    float2 aL[2][4], aH[2][4], bv[2][8];
    ldfrag((const char*)smf, (const char*)smf + 16384, 0, lane, wm, wn, aL[0], aH[0], bv[0]);

    int b = 0;
    for (int c = 0; c < NCH1; c++) {
        const char* As = (const char*)smf + b * 32768;
        const char* Bs = As + 16384;
        #pragma unroll
        for (int ks = 0; ks < 3; ks++) {
            ldfrag(As, Bs, ks + 1, lane, wm, wn, aL[(ks + 1) & 1], aH[(ks + 1) & 1], bv[(ks + 1) & 1]);
            do_mmas(acc, aL[ks & 1], aH[ks & 1], bv[ks & 1]);
        }
        if (c + 1 < NCH1) {
            CPA_WAIT0(); __syncthreads();
            int b2 = b + 2; if (b2 >= 3) b2 -= 3;
            if (c + 2 < NCH1) stage(c + 2, b2);
            int nb = b + 1; if (nb >= 3) nb -= 3;
            const char* As2 = (const char*)smf + nb * 32768;
            ldfrag(As2, As2 + 16384, 0, lane, wm, wn, aL[0], aH[0], bv[0]);
        }
        do_mmas(acc, aL[1], aH[1], bv[1]);
        if (++b == 3) b = 0;
    }

    const float scale = powf(16.f / log1pf(256.f), alphap[0]);
    #pragma unroll
    for (int mi = 0; mi < 4; mi++) {
        const int r0 = wm * 64 + mi * 16 + (lane >> 2);
        const int m0 = m_base + r0, m1 = m0 + 8;
        const float as0 = g_asum[m0], as1 = g_asum[m1];
        float* y0 = g_y + padpix(m0) * 256 + c_base;
        float* y1 = g_y + padpix(m1) * 256 + c_base;
        #pragma unroll
        for (int ni = 0; ni < 8; ni++) {
            const int cl = wn * 64 + ni * 8 + (lane & 3) * 2;
            const float bs0 = sbsum[cl], bs1 = sbsum[cl + 1];
            const float* d = acc[mi][ni];
            const int p0 = kperm(cl), p1 = kperm(cl + 1);
            y0[p0] = tf32r(d[0] * d[0] / (as0 + bs0 - 2.f * d[0] + 1e-5f) * scale);
            y0[p1] = tf32r(d[1] * d[1] / (as0 + bs1 - 2.f * d[1] + 1e-5f) * scale);
            y1[p0] = tf32r(d[2] * d[2] / (as1 + bs0 - 2.f * d[2] + 1e-5f) * scale);
            y1[p1] = tf32r(d[3] * d[3] / (as1 + bs1 - 2.f * d[3] + 1e-5f) * scale);
        }
    }
}

// ---- k2 ----
__global__ __launch_bounds__(128, 2)
void k2_lin(float* __restrict__ out)
{
    extern __shared__ float smf[];
    const uint32_t sb = smem_u32(smf);
    const int tid = threadIdx.x, lane = tid & 31, wid = tid >> 5;
    const int wm = wid >> 1, wn = wid & 1;
    const int m_base = blockIdx.y * 128, c_base = blockIdx.x * 128;

    float acc[4][8][4];
    #pragma unroll
    for (int mi = 0; mi < 4; mi++)
        #pragma unroll
        for (int ni = 0; ni < 8; ni++)
            #pragma unroll
            for (int e = 0; e < 4; e++) acc[mi][ni][e] = 0.f;

    const int t8 = tid & 7, row0 = tid >> 3;
    const float *yb[8], *xb2[8];
    #pragma unroll
    for (int p = 0; p < 8; p++) {
        const size_t pp = padpix(m_base + row0 + 16 * p);
        yb[p]  = g_y  + pp * 256 + t8 * 4;
        xb2[p] = g_xr + pp * 128 + t8 * 4;
    }
    const float* wb0 = g_wlT + (size_t)(c_base + row0) * K2T + t8 * 4;
    const uint32_t du0 = (uint32_t)(row0 * 128 + ((t8 ^ (2 * (row0 & 3))) * 16));

    auto stage = [&](int c, int b) {
        const uint32_t base = sb + (uint32_t)b * 32768u + du0;
        const float* wsrc = wb0 + c * 32;
        if (c < 72) {
            const int khw = c >> 3, c0 = (c & 7) * 32;
            const int dh = khw / 3 - 1, dw = khw % 3 - 1;
            const int yoff = (dh * PH + dw) * 256 + c0;
            #pragma unroll
            for (int p = 0; p < 8; p++) {
                cpa16(base + p * 2048u, yb[p] + yoff);
                cpa16(base + 16384u + p * 2048u, wsrc + p * (16 * K2T));
            }
        } else {
            const int c0 = (c - 72) * 32;
            #pragma unroll
            for (int p = 0; p < 8; p++) {
                cpa16(base + p * 2048u, xb2[p] + c0);
                cpa16(base + 16384u + p * 2048u, wsrc + p * (16 * K2T));
            }
        }
        CPA_COMMIT();
    };

    stage(0, 0); stage(1, 1);
    CPA_WAIT1(); __syncthreads();
    float2 aL[2][4], aH[2][4], bv[2][8];
    ldfrag((const char*)smf, (const char*)smf + 16384, 0, lane, wm, wn, aL[0], aH[0], bv[0]);

    int b = 0;
    for (int c = 0; c < NCH2; c++) {
        const char* As = (const char*)smf + b * 32768;
        const char* Bs = As + 16384;
        #pragma unroll
        for (int ks = 0; ks < 3; ks++) {
            ldfrag(As, Bs, ks + 1, lane, wm, wn, aL[(ks + 1) & 1], aH[(ks + 1) & 1], bv[(ks + 1) & 1]);
            do_mmas(acc, aL[ks & 1], aH[ks & 1], bv[ks & 1]);
        }
        if (c + 1 < NCH2) {
            CPA_WAIT0(); __syncthreads();
            int b2 = b + 2; if (b2 >= 3) b2 -= 3;
            if (c + 2 < NCH2) stage(c + 2, b2);
            int nb = b + 1; if (nb >= 3) nb -= 3;
            const char* As2 = (const char*)smf + nb * 32768;
            ldfrag(As2, As2 + 16384, 0, lane, wm, wn, aL[0], aH[0], bv[0]);
        }
        do_mmas(acc, aL[1], aH[1], bv[1]);
        if (++b == 3) b = 0;
    }

    __syncthreads();
    #pragma unroll
    for (int mi = 0; mi < 4; mi++) {
        const int r0 = wm * 64 + mi * 16 + (lane >> 2);
        #pragma unroll
        for (int ni = 0; ni < 8; ni++) {
            const int cl = wn * 64 + ni * 8 + (lane & 3) * 2;
            const float* d = acc[mi][ni];
            *(float2*)(smf + r0 * 132 + cl) = make_float2(d[0], d[1]);
            *(float2*)(smf + (r0 + 8) * 132 + cl) = make_float2(d[2], d[3]);
        }
    }
    __syncthreads();
    const int n = m_base >> 12, hp = ((m_base >> 6) & 63) >> 1;
    #pragma unroll
    for (int it = 0; it < 8; it++) {
        const int idx = tid + it * 128, pw = idx >> 5, ch = (idx & 31) * 4;
        float4 a0 = *(const float4*)(smf + (2 * pw) * 132 + ch);
        float4 a1 = *(const float4*)(smf + (2 * pw + 1) * 132 + ch);
        float4 a2 = *(const float4*)(smf + (64 + 2 * pw) * 132 + ch);
        float4 a3 = *(const float4*)(smf + (64 + 2 * pw + 1) * 132 + ch);
        *(float4*)(out + ((size_t)((n * 32 + hp) * 32 + pw)) * 256 + c_base + ch) =
            make_float4(0.25f * (a0.x + a1.x + a2.x + a3.x), 0.25f * (a0.y + a1.y + a2.y + a3.y),
                        0.25f * (a0.z + a1.z + a2.z + a3.z), 0.25f * (a0.w + a1.w + a2.w + a3.w));
    }
}

extern "C" void kernel_launch(void* const* d_in, const int* in_sizes, int n_in,
                              void* d_out, int out_size)
{
    const float* x  = (const float*)d_in[0];
    const float* wy = (const float*)d_in[1];
    const float* al = (const float*)d_in[2];
    const float* wl = (const float*)d_in[3];
    const float* wp = (const float*)d_in[4];
    float* out = (float*)d_out;

    cudaFuncSetAttribute(k1_yat, cudaFuncAttributeMaxDynamicSharedMemorySize, 98816);
    cudaFuncSetAttribute(k2_lin, cudaFuncAttributeMaxDynamicSharedMemorySize, 98304);

    k0a_w<<<256, 256>>>(wy, wl, wp);
    k0b_x<<<16384, 256>>>(x);
    k0c_asum<<<512, 256>>>();
    k1_yat<<<dim3(2, 1024), 128, 98816>>>(al);
    k2_lin<<<dim3(2, 1024), 128, 98304>>>(out);
}